// round 7
// baseline (speedup 1.0000x reference)
#include <cuda_runtime.h>
#include <math.h>

#define BB 16
#define LL 1023
#define SS 1024
#define DD 128
#define DVAL 64
#define NDEMO 16
#define HH 8
#define DH 16
#define NLAY 2
#define DFF 512
#define MLPH 256

// ---------------- device scratch (no allocs allowed) ----------------
__device__ float g_x[BB * SS * DD];
__device__ float g_q[BB * SS * DD];
__device__ float g_k[BB * SS * DD];
__device__ float g_v[BB * SS * DD];
__device__ float g_o[BB * SS * DD];
__device__ float g_h[BB * SS * DFF];

__device__ __forceinline__ unsigned f2tf(float x) {
    unsigned r;
    asm("cvt.rna.tf32.f32 %0, %1;" : "=r"(r) : "f"(x));
    return r;
}

__device__ __forceinline__ void mma_tf32(float* c, unsigned a0, unsigned a1,
                                         unsigned a2, unsigned a3,
                                         unsigned b0, unsigned b1) {
    asm("mma.sync.aligned.m16n8k8.row.col.f32.tf32.tf32.f32 "
        "{%0,%1,%2,%3},{%4,%5,%6,%7},{%8,%9},{%0,%1,%2,%3};"
        : "+f"(c[0]), "+f"(c[1]), "+f"(c[2]), "+f"(c[3])
        : "r"(a0), "r"(a1), "r"(a2), "r"(a3), "r"(b0), "r"(b1));
}

__device__ __forceinline__ unsigned smem_u32(const void* p) {
    return (unsigned)__cvta_generic_to_shared(p);
}

// ldmatrix x4: returns (m0,m1,m2,m3); for fp32-as-2xb16 8x4-fp32 tiles this is
// m0=A[g][tg], m1=A[g][tg+4], m2=A[g+8][tg], m3=A[g+8][tg+4]
__device__ __forceinline__ void ldsm_x4(unsigned& r0, unsigned& r1,
                                        unsigned& r2, unsigned& r3, unsigned a) {
    asm volatile("ldmatrix.sync.aligned.m8n8.x4.shared.b16 {%0,%1,%2,%3}, [%4];"
        : "=r"(r0), "=r"(r1), "=r"(r2), "=r"(r3) : "r"(a));
}

// ---------------- GEMM tile: 32 rows x 128 cols, 256 threads, 8 warps ----------------
// warp w: mq = w>>2 (m16 half), nq = w&3 (n32 quarter)
__device__ __forceinline__ void stage_As32(unsigned (*As)[36], const float* Ag,
                                           int lda, int t) {
    int r = t >> 3, c0 = (t & 7) * 4;
    float4 v = *(const float4*)(Ag + (size_t)r * lda + c0);
    uint4 u = {f2tf(v.x), f2tf(v.y), f2tf(v.z), f2tf(v.w)};
    *(uint4*)&As[r][c0] = u;
}

__device__ __forceinline__ void stage_Bs32(unsigned (*Bs)[136], const float* Wg,
                                           int ldw, int t) {
    int r = t >> 3, f0 = t & 7;
    #pragma unroll
    for (int j = 0; j < 4; j++) {
        int c = (f0 + j * 8) * 4;
        float4 v = *(const float4*)(Wg + (size_t)r * ldw + c);
        uint4 u = {f2tf(v.x), f2tf(v.y), f2tf(v.z), f2tf(v.w)};
        *(uint4*)&Bs[r][c] = u;
    }
}

__device__ __forceinline__ void compute_chunk32(float (*acc)[4],
        const unsigned (*As)[36], const unsigned (*Bs)[136],
        int mq, int nq, int lane, int g, int tg) {
    int arow = mq * 16 + (lane & 7) + ((lane & 16) >> 1);
    int acol = ((lane >> 3) & 1) * 4;
    #pragma unroll
    for (int ks = 0; ks < 4; ks++) {
        unsigned a0, a1, a2, a3;
        ldsm_x4(a0, a2, a1, a3, smem_u32(&As[arow][ks * 8 + acol]));
        #pragma unroll
        for (int nt = 0; nt < 4; nt++) {
            unsigned b0 = Bs[ks * 8 + tg][nq * 32 + nt * 8 + g];
            unsigned b1 = Bs[ks * 8 + tg + 4][nq * 32 + nt * 8 + g];
            mma_tf32(acc[nt], a0, a1, a2, a3, b0, b1);
        }
    }
}

__device__ __forceinline__ void gemm_mainloop32(
    float (*acc)[4], unsigned (*As)[36], unsigned (*Bs)[136],
    const float* Ag, int lda, const float* Wg, int ldw, int nK,
    int t, int mq, int nq, int lane, int g, int tg) {
    for (int kc = 0; kc < nK; kc++) {
        __syncthreads();
        stage_As32(As, Ag + kc * 32, lda, t);
        stage_Bs32(Bs, Wg + (size_t)kc * 32 * ldw, ldw, t);
        __syncthreads();
        compute_chunk32(acc, As, Bs, mq, nq, lane, g, tg);
    }
}

// ---------------- embedding ----------------
__global__ __launch_bounds__(256) void embed_kernel(
    const float* __restrict__ demo, const float* __restrict__ times,
    const float* __restrict__ values, const float* __restrict__ timescales,
    const float* __restrict__ W_demo, const float* __restrict__ b_demo,
    const float* __restrict__ W_val, const float* __restrict__ b_val,
    const int* __restrict__ length) {
    int idx = blockIdx.x * blockDim.x + threadIdx.x;
    if (idx >= BB * SS * DD) return;
    int d = idx % DD;
    int s = (idx / DD) % SS;
    int b = idx / (DD * SS);
    if (s > length[b]) return;
    float out;
    if (s == 0) {
        float acc = b_demo[d];
        #pragma unroll
        for (int k = 0; k < NDEMO; k++) acc += demo[b * NDEMO + k] * W_demo[k * DD + d];
        out = acc;
    } else {
        int t = s - 1;
        float acc = b_val[d];
        const float4* vrow = (const float4*)(values + (b * LL + t) * DVAL);
        #pragma unroll
        for (int k4 = 0; k4 < DVAL / 4; k4++) {
            float4 vv = vrow[k4];
            acc += vv.x * W_val[(k4 * 4 + 0) * DD + d];
            acc += vv.y * W_val[(k4 * 4 + 1) * DD + d];
            acc += vv.z * W_val[(k4 * 4 + 2) * DD + d];
            acc += vv.w * W_val[(k4 * 4 + 3) * DD + d];
        }
        float tm = times[b * LL + t];
        float st = tm / timescales[d & 63];
        out = acc + ((d < 64) ? __sinf(st) : __cosf(st));
    }
    g_x[idx] = out;
}

// ---------------- QKV: grid (tiles32, 3) ----------------
__global__ __launch_bounds__(256) void qkv_mma_kernel(
    const int* __restrict__ length,
    const float* __restrict__ Wq, const float* __restrict__ bq,
    const float* __restrict__ Wk, const float* __restrict__ bk,
    const float* __restrict__ Wv, const float* __restrict__ bv) {
    int row0 = blockIdx.x * 32;
    int b = row0 >> 10;
    int valid_len = length[b] + 1;
    if ((row0 & (SS - 1)) >= valid_len) return;
    int wi = blockIdx.y;
    const float* W = (wi == 0) ? Wq : (wi == 1) ? Wk : Wv;
    const float* bias = (wi == 0) ? bq : (wi == 1) ? bk : bv;
    float* out = (wi == 0) ? g_q : (wi == 1) ? g_k : g_v;

    __shared__ unsigned As[32][36];
    __shared__ unsigned Bs[32][136];
    int t = threadIdx.x, w = t >> 5, lane = t & 31;
    int g = lane >> 2, tg = lane & 3, mq = w >> 2, nq = w & 3;

    float acc[4][4];
    #pragma unroll
    for (int i = 0; i < 4; i++) acc[i][0] = acc[i][1] = acc[i][2] = acc[i][3] = 0.f;

    gemm_mainloop32(acc, As, Bs, g_x + (size_t)row0 * DD, DD, W, DD, 4,
                    t, mq, nq, lane, g, tg);

    int r0 = row0 + mq * 16 + g, r1 = r0 + 8;
    #pragma unroll
    for (int nt = 0; nt < 4; nt++) {
        int col = nq * 32 + nt * 8 + 2 * tg;
        float2 bi = *(const float2*)&bias[col];
        float2 lo = {acc[nt][0] + bi.x, acc[nt][1] + bi.y};
        float2 hi = {acc[nt][2] + bi.x, acc[nt][3] + bi.y};
        *(float2*)&out[(size_t)r0 * DD + col] = lo;
        *(float2*)&out[(size_t)r1 * DD + col] = hi;
    }
}

// ---------------- flash attention: 64-key chunks, double-buffered ----------------
__device__ __forceinline__ void attn_stage(unsigned (*Kb)[72], unsigned (*Vb)[24],
                                           int b, int h, int c, int t) {
    int key = t >> 1, d8 = (t & 1) << 3;
    int src = (b * SS + c * 64 + key) * DD + h * DH + d8;
    float4 ka = *(const float4*)(g_k + src);
    float4 kb = *(const float4*)(g_k + src + 4);
    Kb[d8 + 0][key] = f2tf(ka.x); Kb[d8 + 1][key] = f2tf(ka.y);
    Kb[d8 + 2][key] = f2tf(ka.z); Kb[d8 + 3][key] = f2tf(ka.w);
    Kb[d8 + 4][key] = f2tf(kb.x); Kb[d8 + 5][key] = f2tf(kb.y);
    Kb[d8 + 6][key] = f2tf(kb.z); Kb[d8 + 7][key] = f2tf(kb.w);
    float4 va = *(const float4*)(g_v + src);
    float4 vb = *(const float4*)(g_v + src + 4);
    uint4 u0 = {f2tf(va.x), f2tf(va.y), f2tf(va.z), f2tf(va.w)};
    uint4 u1 = {f2tf(vb.x), f2tf(vb.y), f2tf(vb.z), f2tf(vb.w)};
    *(uint4*)&Vb[key][d8] = u0;
    *(uint4*)&Vb[key][d8 + 4] = u1;
}

__global__ __launch_bounds__(128) void attn_mma_kernel(const int* __restrict__ length) {
    const int qt = blockIdx.x, h = blockIdx.y, b = blockIdx.z;
    int valid_len = length[b] + 1;
    int q0 = qt * 64;
    if (q0 >= valid_len) return;

    __shared__ unsigned Ks[2][16][72];
    __shared__ unsigned Vs[2][64][24];
    __shared__ unsigned Ps[64][68];

    int t = threadIdx.x;
    int w = t >> 5, lane = t & 31;
    int g = lane >> 2, tg = lane & 3;
    int qrow_base = b * SS + q0 + w * 16;

    unsigned qa[2][4];
    #pragma unroll
    for (int ks = 0; ks < 2; ks++) {
        int r_lo = (qrow_base + g) * DD + h * DH + ks * 8 + tg;
        int r_hi = (qrow_base + g + 8) * DD + h * DH + ks * 8 + tg;
        qa[ks][0] = f2tf(g_q[r_lo] * 0.25f);
        qa[ks][1] = f2tf(g_q[r_hi] * 0.25f);
        qa[ks][2] = f2tf(g_q[r_lo + 4] * 0.25f);
        qa[ks][3] = f2tf(g_q[r_hi + 4] * 0.25f);
    }

    float m0 = -1e30f, m1 = -1e30f, l0 = 0.f, l1 = 0.f;
    float oc[2][4];
    #pragma unroll
    for (int i = 0; i < 2; i++)
        #pragma unroll
        for (int j = 0; j < 4; j++) oc[i][j] = 0.f;

    int nch = (valid_len + 63) >> 6;
    int prow = w * 16 + (lane & 7) + ((lane & 16) >> 1);
    int pcol = ((lane >> 3) & 1) * 4;

    attn_stage(Ks[0], Vs[0], b, h, 0, t);
    __syncthreads();

    for (int c = 0; c < nch; c++) {
        int bi = c & 1;
        if (c + 1 < nch) attn_stage(Ks[bi ^ 1], Vs[bi ^ 1], b, h, c + 1, t);

        float sc[8][4];
        #pragma unroll
        for (int nt = 0; nt < 8; nt++) {
            sc[nt][0] = sc[nt][1] = sc[nt][2] = sc[nt][3] = 0.f;
            #pragma unroll
            for (int ks = 0; ks < 2; ks++) {
                unsigned b0 = Ks[bi][ks * 8 + tg][nt * 8 + g];
                unsigned b1 = Ks[bi][ks * 8 + tg + 4][nt * 8 + g];
                mma_tf32(sc[nt], qa[ks][0], qa[ks][1], qa[ks][2], qa[ks][3], b0, b1);
            }
        }

        int limit = valid_len - c * 64;
        float rmax0 = -1e30f, rmax1 = -1e30f;
        #pragma unroll
        for (int nt = 0; nt < 8; nt++) {
            int col0 = nt * 8 + 2 * tg;
            int col1 = col0 + 1;
            sc[nt][0] = (col0 < limit) ? sc[nt][0] : -1e30f;
            sc[nt][1] = (col1 < limit) ? sc[nt][1] : -1e30f;
            sc[nt][2] = (col0 < limit) ? sc[nt][2] : -1e30f;
            sc[nt][3] = (col1 < limit) ? sc[nt][3] : -1e30f;
            rmax0 = fmaxf(rmax0, fmaxf(sc[nt][0], sc[nt][1]));
            rmax1 = fmaxf(rmax1, fmaxf(sc[nt][2], sc[nt][3]));
        }
        rmax0 = fmaxf(rmax0, __shfl_xor_sync(0xffffffff, rmax0, 1));
        rmax0 = fmaxf(rmax0, __shfl_xor_sync(0xffffffff, rmax0, 2));
        rmax1 = fmaxf(rmax1, __shfl_xor_sync(0xffffffff, rmax1, 1));
        rmax1 = fmaxf(rmax1, __shfl_xor_sync(0xffffffff, rmax1, 2));

        float mn0 = fmaxf(m0, rmax0), mn1 = fmaxf(m1, rmax1);
        float scale0 = __expf(m0 - mn0), scale1 = __expf(m1 - mn1);

        float ls0 = 0.f, ls1 = 0.f;
        #pragma unroll
        for (int nt = 0; nt < 8; nt++) {
            float p0 = __expf(sc[nt][0] - mn0);
            float p1 = __expf(sc[nt][1] - mn0);
            float p2 = __expf(sc[nt][2] - mn1);
            float p3 = __expf(sc[nt][3] - mn1);
            ls0 += p0 + p1;
            ls1 += p2 + p3;
            int colw = nt * 8 + 2 * tg;
            uint2 lo = {__float_as_uint(p0), __float_as_uint(p1)};
            uint2 hi = {__float_as_uint(p2), __float_as_uint(p3)};
            *(uint2*)&Ps[w * 16 + g][colw] = lo;
            *(uint2*)&Ps[w * 16 + g + 8][colw] = hi;
        }
        ls0 += __shfl_xor_sync(0xffffffff, ls0, 1);
        ls0 += __shfl_xor_sync(0xffffffff, ls0, 2);
        ls1 += __shfl_xor_sync(0xffffffff, ls1, 1);
        ls1 += __shfl_xor_sync(0xffffffff, ls1, 2);
        l0 = l0 * scale0 + ls0;
        l1 = l1 * scale1 + ls1;
        #pragma unroll
        for (int mt = 0; mt < 2; mt++) {
            oc[mt][0] *= scale0; oc[mt][1] *= scale0;
            oc[mt][2] *= scale1; oc[mt][3] *= scale1;
        }
        m0 = mn0; m1 = mn1;
        __syncwarp();

        #pragma unroll
        for (int j = 0; j < 8; j++) {
            unsigned pa0, pa1, pa2, pa3;
            ldsm_x4(pa0, pa2, pa1, pa3, smem_u32(&Ps[prow][j * 8 + pcol]));
            #pragma unroll
            for (int mt = 0; mt < 2; mt++) {
                unsigned vb0 = Vs[bi][j * 8 + tg][mt * 8 + g];
                unsigned vb1 = Vs[bi][j * 8 + tg + 4][mt * 8 + g];
                mma_tf32(oc[mt], pa0, pa1, pa2, pa3, vb0, vb1);
            }
        }
        __syncthreads();
    }

    float inv0 = 1.f / l0, inv1 = 1.f / l1;
    #pragma unroll
    for (int mt = 0; mt < 2; mt++) {
        int col = h * DH + mt * 8 + 2 * tg;
        float2 lo = {oc[mt][0] * inv0, oc[mt][1] * inv0};
        float2 hi = {oc[mt][2] * inv1, oc[mt][3] * inv1};
        *(float2*)&g_o[(qrow_base + g) * DD + col] = lo;
        *(float2*)&g_o[(qrow_base + g + 8) * DD + col] = hi;
    }
}

// ---------------- O-proj + residual + LN1 ----------------
__global__ __launch_bounds__(256) void oproj_ln_mma_kernel(
    const int* __restrict__ length,
    const float* __restrict__ Wo, const float* __restrict__ bo,
    const float* __restrict__ g1, const float* __restrict__ be1) {
    int row0 = blockIdx.x * 32;
    int b = row0 >> 10;
    int valid_len = length[b] + 1;
    if ((row0 & (SS - 1)) >= valid_len) return;

    __shared__ unsigned As[32][36];
    __shared__ unsigned Bs[32][136];
    __shared__ float redS[4][32];
    __shared__ float redQ[4][32];
    int t = threadIdx.x, w = t >> 5, lane = t & 31;
    int g = lane >> 2, tg = lane & 3, mq = w >> 2, nq = w & 3;

    float acc[4][4];
    #pragma unroll
    for (int i = 0; i < 4; i++) acc[i][0] = acc[i][1] = acc[i][2] = acc[i][3] = 0.f;

    gemm_mainloop32(acc, As, Bs, g_o + (size_t)row0 * DD, DD, Wo, DD, 4,
                    t, mq, nq, lane, g, tg);

    int rr0 = mq * 16 + g, rr1 = rr0 + 8;
    int r0 = row0 + rr0, r1 = row0 + rr1;
    float rs0 = 0.f, rq0 = 0.f, rs1 = 0.f, rq1 = 0.f;
    #pragma unroll
    for (int nt = 0; nt < 4; nt++) {
        int col = nq * 32 + nt * 8 + 2 * tg;
        float2 bi = *(const float2*)&bo[col];
        float2 e0 = *(const float2*)&g_x[(size_t)r0 * DD + col];
        float2 e1 = *(const float2*)&g_x[(size_t)r1 * DD + col];
        acc[nt][0] += bi.x + e0.x;
        acc[nt][1] += bi.y + e0.y;
        acc[nt][2] += bi.x + e1.x;
        acc[nt][3] += bi.y + e1.y;
        rs0 += acc[nt][0] + acc[nt][1];
        rq0 += acc[nt][0] * acc[nt][0] + acc[nt][1] * acc[nt][1];
        rs1 += acc[nt][2] + acc[nt][3];
        rq1 += acc[nt][2] * acc[nt][2] + acc[nt][3] * acc[nt][3];
    }
    rs0 += __shfl_xor_sync(0xffffffff, rs0, 1);
    rs0 += __shfl_xor_sync(0xffffffff, rs0, 2);
    rq0 += __shfl_xor_sync(0xffffffff, rq0, 1);
    rq0 += __shfl_xor_sync(0xffffffff, rq0, 2);
    rs1 += __shfl_xor_sync(0xffffffff, rs1, 1);
    rs1 += __shfl_xor_sync(0xffffffff, rs1, 2);
    rq1 += __shfl_xor_sync(0xffffffff, rq1, 1);
    rq1 += __shfl_xor_sync(0xffffffff, rq1, 2);
    if (tg == 0) {
        redS[nq][rr0] = rs0; redS[nq][rr1] = rs1;
        redQ[nq][rr0] = rq0; redQ[nq][rr1] = rq1;
    }
    __syncthreads();
    float mu0 = (redS[0][rr0] + redS[1][rr0] + redS[2][rr0] + redS[3][rr0]) * (1.f / DD);
    float mu1 = (redS[0][rr1] + redS[1][rr1] + redS[2][rr1] + redS[3][rr1]) * (1.f / DD);
    float v0 = fmaxf((redQ[0][rr0] + redQ[1][rr0] + redQ[2][rr0] + redQ[3][rr0]) * (1.f / DD) - mu0 * mu0, 0.f);
    float v1 = fmaxf((redQ[0][rr1] + redQ[1][rr1] + redQ[2][rr1] + redQ[3][rr1]) * (1.f / DD) - mu1 * mu1, 0.f);
    float rst0 = rsqrtf(v0 + 1e-3f), rst1 = rsqrtf(v1 + 1e-3f);
    #pragma unroll
    for (int nt = 0; nt < 4; nt++) {
        int col = nq * 32 + nt * 8 + 2 * tg;
        float2 gm = *(const float2*)&g1[col];
        float2 bt = *(const float2*)&be1[col];
        float2 lo = {(acc[nt][0] - mu0) * rst0 * gm.x + bt.x,
                     (acc[nt][1] - mu0) * rst0 * gm.y + bt.y};
        float2 hi = {(acc[nt][2] - mu1) * rst1 * gm.x + bt.x,
                     (acc[nt][3] - mu1) * rst1 * gm.y + bt.y};
        *(float2*)&g_x[(size_t)r0 * DD + col] = lo;
        *(float2*)&g_x[(size_t)r1 * DD + col] = hi;
    }
}

// ---------------- FFN1: grid (tiles32, 4) ----------------
__global__ __launch_bounds__(256) void ffn1_mma_kernel(
    const int* __restrict__ length,
    const float* __restrict__ W1, const float* __restrict__ b1) {
    int row0 = blockIdx.x * 32;
    int b = row0 >> 10;
    int valid_len = length[b] + 1;
    if ((row0 & (SS - 1)) >= valid_len) return;
    int ncol0 = blockIdx.y * 128;

    __shared__ unsigned As[32][36];
    __shared__ unsigned Bs[32][136];
    int t = threadIdx.x, w = t >> 5, lane = t & 31;
    int g = lane >> 2, tg = lane & 3, mq = w >> 2, nq = w & 3;

    float acc[4][4];
    #pragma unroll
    for (int i = 0; i < 4; i++) acc[i][0] = acc[i][1] = acc[i][2] = acc[i][3] = 0.f;

    gemm_mainloop32(acc, As, Bs, g_x + (size_t)row0 * DD, DD, W1 + ncol0, DFF, 4,
                    t, mq, nq, lane, g, tg);

    int r0 = row0 + mq * 16 + g, r1 = r0 + 8;
    #pragma unroll
    for (int nt = 0; nt < 4; nt++) {
        int col = ncol0 + nq * 32 + nt * 8 + 2 * tg;
        float2 bi = *(const float2*)&b1[col];
        float2 lo = {fmaxf(acc[nt][0] + bi.x, 0.f), fmaxf(acc[nt][1] + bi.y, 0.f)};
        float2 hi = {fmaxf(acc[nt][2] + bi.x, 0.f), fmaxf(acc[nt][3] + bi.y, 0.f)};
        *(float2*)&g_h[(size_t)r0 * DFF + col] = lo;
        *(float2*)&g_h[(size_t)r1 * DFF + col] = hi;
    }
}

// ---------------- FFN2 + residual + LN2 ----------------
__global__ __launch_bounds__(256) void ffn2_ln_mma_kernel(
    const int* __restrict__ length,
    const float* __restrict__ W2, const float* __restrict__ b2,
    const float* __restrict__ g2, const float* __restrict__ be2) {
    int row0 = blockIdx.x * 32;
    int b = row0 >> 10;
    int valid_len = length[b] + 1;
    if ((row0 & (SS - 1)) >= valid_len) return;

    __shared__ unsigned As[32][36];
    __shared__ unsigned Bs[32][136];
    __shared__ float redS[4][32];
    __shared__ float redQ[4][32];
    int t = threadIdx.x, w = t >> 5, lane = t & 31;
    int g = lane >> 2, tg = lane & 3, mq = w >> 2, nq = w & 3;

    float acc[4][4];
    #pragma unroll
    for (int i = 0; i < 4; i++) acc[i][0] = acc[i][1] = acc[i][2] = acc[i][3] = 0.f;

    gemm_mainloop32(acc, As, Bs, g_h + (size_t)row0 * DFF, DFF, W2, DD, DFF / 32,
                    t, mq, nq, lane, g, tg);

    int rr0 = mq * 16 + g, rr1 = rr0 + 8;
    int r0 = row0 + rr0, r1 = row0 + rr1;
    float rs0 = 0.f, rq0 = 0.f, rs1 = 0.f, rq1 = 0.f;
    #pragma unroll
    for (int nt = 0; nt < 4; nt++) {
        int col = nq * 32 + nt * 8 + 2 * tg;
        float2 bi = *(const float2*)&b2[col];
        float2 e0 = *(const float2*)&g_x[(size_t)r0 * DD + col];
        float2 e1 = *(const float2*)&g_x[(size_t)r1 * DD + col];
        acc[nt][0] += bi.x + e0.x;
        acc[nt][1] += bi.y + e0.y;
        acc[nt][2] += bi.x + e1.x;
        acc[nt][3] += bi.y + e1.y;
        rs0 += acc[nt][0] + acc[nt][1];
        rq0 += acc[nt][0] * acc[nt][0] + acc[nt][1] * acc[nt][1];
        rs1 += acc[nt][2] + acc[nt][3];
        rq1 += acc[nt][2] * acc[nt][2] + acc[nt][3] * acc[nt][3];
    }
    rs0 += __shfl_xor_sync(0xffffffff, rs0, 1);
    rs0 += __shfl_xor_sync(0xffffffff, rs0, 2);
    rq0 += __shfl_xor_sync(0xffffffff, rq0, 1);
    rq0 += __shfl_xor_sync(0xffffffff, rq0, 2);
    rs1 += __shfl_xor_sync(0xffffffff, rs1, 1);
    rs1 += __shfl_xor_sync(0xffffffff, rs1, 2);
    rq1 += __shfl_xor_sync(0xffffffff, rq1, 1);
    rq1 += __shfl_xor_sync(0xffffffff, rq1, 2);
    if (tg == 0) {
        redS[nq][rr0] = rs0; redS[nq][rr1] = rs1;
        redQ[nq][rr0] = rq0; redQ[nq][rr1] = rq1;
    }
    __syncthreads();
    float mu0 = (redS[0][rr0] + redS[1][rr0] + redS[2][rr0] + redS[3][rr0]) * (1.f / DD);
    float mu1 = (redS[0][rr1] + redS[1][rr1] + redS[2][rr1] + redS[3][rr1]) * (1.f / DD);
    float v0 = fmaxf((redQ[0][rr0] + redQ[1][rr0] + redQ[2][rr0] + redQ[3][rr0]) * (1.f / DD) - mu0 * mu0, 0.f);
    float v1 = fmaxf((redQ[0][rr1] + redQ[1][rr1] + redQ[2][rr1] + redQ[3][rr1]) * (1.f / DD) - mu1 * mu1, 0.f);
    float rst0 = rsqrtf(v0 + 1e-3f), rst1 = rsqrtf(v1 + 1e-3f);
    #pragma unroll
    for (int nt = 0; nt < 4; nt++) {
        int col = nq * 32 + nt * 8 + 2 * tg;
        float2 gm = *(const float2*)&g2[col];
        float2 bt = *(const float2*)&be2[col];
        float2 lo = {(acc[nt][0] - mu0) * rst0 * gm.x + bt.x,
                     (acc[nt][1] - mu0) * rst0 * gm.y + bt.y};
        float2 hi = {(acc[nt][2] - mu1) * rst1 * gm.x + bt.x,
                     (acc[nt][3] - mu1) * rst1 * gm.y + bt.y};
        *(float2*)&g_x[(size_t)r0 * DD + col] = lo;
        *(float2*)&g_x[(size_t)r1 * DD + col] = hi;
    }
}

// ---------------- masked mean-pool + MLP head + sigmoid ----------------
__global__ __launch_bounds__(256) void head_kernel(
    const int* __restrict__ length,
    const float* __restrict__ Wm1, const float* __restrict__ bm1,
    const float* __restrict__ Wm2, const float* __restrict__ bm2,
    float* __restrict__ out) {
    int b = blockIdx.x;
    int t = threadIdx.x;
    __shared__ float part[2][DD];
    __shared__ float agg[DD];
    __shared__ float hh[MLPH];
    __shared__ float red[8];
    int cnt = length[b] + 1;
    int d = t & 127, grp = t >> 7;
    float s0 = 0.f, s1 = 0.f, s2 = 0.f, s3 = 0.f;
    int ss = grp;
    for (; ss + 6 < cnt; ss += 8) {
        s0 += g_x[(b * SS + ss) * DD + d];
        s1 += g_x[(b * SS + ss + 2) * DD + d];
        s2 += g_x[(b * SS + ss + 4) * DD + d];
        s3 += g_x[(b * SS + ss + 6) * DD + d];
    }
    for (; ss < cnt; ss += 2) s0 += g_x[(b * SS + ss) * DD + d];
    part[grp][d] = s0 + s1 + s2 + s3;
    __syncthreads();
    if (t < DD) agg[t] = (part[0][t] + part[1][t]) / (float)cnt;
    __syncthreads();
    {
        float acc = bm1[t];
        #pragma unroll 8
        for (int k = 0; k < DD; k++) acc += agg[k] * Wm1[k * MLPH + t];
        hh[t] = fmaxf(acc, 0.f);
    }
    __syncthreads();
    float v = hh[t] * Wm2[t];
    #pragma unroll
    for (int o = 16; o > 0; o >>= 1) v += __shfl_xor_sync(0xffffffff, v, o);
    if ((t & 31) == 0) red[t >> 5] = v;
    __syncthreads();
    if (t == 0) {
        float s = 0.f;
        #pragma unroll
        for (int i = 0; i < 8; i++) s += red[i];
        s += bm2[0];
        out[b] = 1.f / (1.f + __expf(-s));
    }
}

// ---------------- launch ----------------
extern "C" void kernel_launch(void* const* d_in, const int* in_sizes, int n_in,
                              void* d_out, int out_size) {
    (void)in_sizes; (void)n_in; (void)out_size;
    const float* demo       = (const float*)d_in[0];
    const float* times      = (const float*)d_in[1];
    const float* values     = (const float*)d_in[2];
    const int*   length     = (const int*)d_in[3];
    const float* timescales = (const float*)d_in[4];
    const float* W_demo = (const float*)d_in[5];
    const float* b_demo = (const float*)d_in[6];
    const float* W_val  = (const float*)d_in[7];
    const float* b_val  = (const float*)d_in[8];
    const float* Wq = (const float*)d_in[9];
    const float* bq = (const float*)d_in[10];
    const float* Wk = (const float*)d_in[11];
    const float* bk = (const float*)d_in[12];
    const float* Wv = (const float*)d_in[13];
    const float* bv = (const float*)d_in[14];
    const float* Wo = (const float*)d_in[15];
    const float* bo = (const float*)d_in[16];
    const float* ln1g = (const float*)d_in[17];
    const float* ln1b = (const float*)d_in[18];
    const float* W1 = (const float*)d_in[19];
    const float* b1 = (const float*)d_in[20];
    const float* W2 = (const float*)d_in[21];
    const float* b2 = (const float*)d_in[22];
    const float* ln2g = (const float*)d_in[23];
    const float* ln2b = (const float*)d_in[24];
    const float* Wm1 = (const float*)d_in[25];
    const float* bm1 = (const float*)d_in[26];
    const float* Wm2 = (const float*)d_in[27];
    const float* bm2 = (const float*)d_in[28];
    float* out = (float*)d_out;

    embed_kernel<<<(BB * SS * DD + 255) / 256, 256>>>(
        demo, times, values, timescales, W_demo, b_demo, W_val, b_val, length);

    int nt32 = BB * SS / 32;
    for (int l = 0; l < NLAY; l++) {
        dim3 gq(nt32, 3);
        qkv_mma_kernel<<<gq, 256>>>(length,
            Wq + l * DD * DD, bq + l * DD,
            Wk + l * DD * DD, bk + l * DD,
            Wv + l * DD * DD, bv + l * DD);
        dim3 ag(SS / 64, HH, BB);
        attn_mma_kernel<<<ag, 128>>>(length);
        oproj_ln_mma_kernel<<<nt32, 256>>>(length,
            Wo + l * DD * DD, bo + l * DD, ln1g + l * DD, ln1b + l * DD);
        dim3 gf(nt32, 4);
        ffn1_mma_kernel<<<gf, 256>>>(length, W1 + l * DD * DFF, b1 + l * DFF);
        ffn2_ln_mma_kernel<<<nt32, 256>>>(length,
            W2 + l * DFF * DD, b2 + l * DD, ln2g + l * DD, ln2b + l * DD);
    }

    head_kernel<<<BB, 256>>>(length, Wm1, bm1, Wm2, bm2, out);
}

// round 8
// speedup vs baseline: 1.1172x; 1.1172x over previous
#include <cuda_runtime.h>
#include <math.h>

#define BB 16
#define LL 1023
#define SS 1024
#define DD 128
#define DVAL 64
#define NDEMO 16
#define HH 8
#define DH 16
#define NLAY 2
#define DFF 512
#define MLPH 256

#define AS_ELEMS (64 * 36)
#define BS_ELEMS (32 * 136)
#define GEMM_SMEM_BYTES ((2 * AS_ELEMS + 2 * BS_ELEMS) * 4)

// ---------------- device scratch (no allocs allowed) ----------------
__device__ float g_x[BB * SS * DD];
__device__ float g_q[BB * SS * DD];
__device__ float g_k[BB * SS * DD];
__device__ float g_v[BB * SS * DD];
__device__ float g_o[BB * SS * DD];
__device__ float g_h[BB * SS * DFF];

__device__ __forceinline__ unsigned f2tf(float x) {
    unsigned r;
    asm("cvt.rna.tf32.f32 %0, %1;" : "=r"(r) : "f"(x));
    return r;
}

__device__ __forceinline__ void mma_tf32(float* c, unsigned a0, unsigned a1,
                                         unsigned a2, unsigned a3,
                                         unsigned b0, unsigned b1) {
    asm("mma.sync.aligned.m16n8k8.row.col.f32.tf32.tf32.f32 "
        "{%0,%1,%2,%3},{%4,%5,%6,%7},{%8,%9},{%0,%1,%2,%3};"
        : "+f"(c[0]), "+f"(c[1]), "+f"(c[2]), "+f"(c[3])
        : "r"(a0), "r"(a1), "r"(a2), "r"(a3), "r"(b0), "r"(b1));
}

__device__ __forceinline__ unsigned smem_u32(const void* p) {
    return (unsigned)__cvta_generic_to_shared(p);
}

__device__ __forceinline__ void cp_async16(unsigned s, const void* g) {
    asm volatile("cp.async.ca.shared.global [%0], [%1], 16;" :: "r"(s), "l"(g));
}
#define CP_COMMIT() asm volatile("cp.async.commit_group;" ::: "memory")
#define CP_WAIT1() asm volatile("cp.async.wait_group 1;" ::: "memory")
#define CP_WAIT0() asm volatile("cp.async.wait_group 0;" ::: "memory")

// ---------------- GEMM tile: 64 rows x 128 cols, 256 threads ----------------
__device__ __forceinline__ void compute_chunk(float (*acc)[4],
                                              const unsigned (*As)[36],
                                              const unsigned (*Bs)[136],
                                              int mq, int nh, int g, int tg) {
    int mr = mq * 16;
    #pragma unroll
    for (int ks = 0; ks < 4; ks++) {
        unsigned a0 = As[mr + g][ks * 8 + tg];
        unsigned a1 = As[mr + g + 8][ks * 8 + tg];
        unsigned a2 = As[mr + g][ks * 8 + tg + 4];
        unsigned a3 = As[mr + g + 8][ks * 8 + tg + 4];
        #pragma unroll
        for (int nt = 0; nt < 8; nt++) {
            unsigned b0 = Bs[ks * 8 + tg][nh * 64 + nt * 8 + g];
            unsigned b1 = Bs[ks * 8 + tg + 4][nh * 64 + nt * 8 + g];
            mma_tf32(acc[nt], a0, a1, a2, a3, b0, b1);
        }
    }
}

// cp.async double-buffered GEMM mainloop over nK k-chunks of 32.
__device__ __forceinline__ void gemm_mainloop_cp(
    float (*acc)[4], unsigned* smemu,
    const float* Ag, int lda, const float* Wg, int ldw, int nK,
    int t, int mq, int nh, int g, int tg) {
    unsigned (*As0)[36] = (unsigned(*)[36])smemu;
    unsigned (*As1)[36] = (unsigned(*)[36])(smemu + AS_ELEMS);
    unsigned (*Bs0)[136] = (unsigned(*)[136])(smemu + 2 * AS_ELEMS);
    unsigned (*Bs1)[136] = (unsigned(*)[136])(smemu + 2 * AS_ELEMS + BS_ELEMS);

    int ra = t >> 2, c0 = (t & 3) * 8;
    int rb = t >> 3, f0 = t & 7;

    auto stage = [&](int kc, unsigned (*As)[36], unsigned (*Bs)[136]) {
        const float* ap = Ag + (size_t)ra * lda + kc * 32 + c0;
        cp_async16(smem_u32(&As[ra][c0]), ap);
        cp_async16(smem_u32(&As[ra][c0 + 4]), ap + 4);
        const float* bp = Wg + (size_t)(kc * 32 + rb) * ldw;
        #pragma unroll
        for (int j = 0; j < 4; j++) {
            int c = (f0 + j * 8) * 4;
            cp_async16(smem_u32(&Bs[rb][c]), bp + c);
        }
        CP_COMMIT();
    };

    stage(0, As0, Bs0);
    for (int kc = 0; kc < nK; kc++) {
        unsigned (*Ac)[36] = (kc & 1) ? As1 : As0;
        unsigned (*Bc)[136] = (kc & 1) ? Bs1 : Bs0;
        if (kc + 1 < nK) {
            stage(kc + 1, (kc & 1) ? As0 : As1, (kc & 1) ? Bs0 : Bs1);
            CP_WAIT1();
        } else {
            CP_WAIT0();
        }
        __syncthreads();
        compute_chunk(acc, Ac, Bc, mq, nh, g, tg);
        __syncthreads();
    }
}

// ---------------- embedding ----------------
__global__ __launch_bounds__(256) void embed_kernel(
    const float* __restrict__ demo, const float* __restrict__ times,
    const float* __restrict__ values, const float* __restrict__ timescales,
    const float* __restrict__ W_demo, const float* __restrict__ b_demo,
    const float* __restrict__ W_val, const float* __restrict__ b_val,
    const int* __restrict__ length) {
    int idx = blockIdx.x * blockDim.x + threadIdx.x;
    if (idx >= BB * SS * DD) return;
    int d = idx % DD;
    int s = (idx / DD) % SS;
    int b = idx / (DD * SS);
    if (s > length[b]) return;
    float out;
    if (s == 0) {
        float acc = b_demo[d];
        #pragma unroll
        for (int k = 0; k < NDEMO; k++) acc += demo[b * NDEMO + k] * W_demo[k * DD + d];
        out = acc;
    } else {
        int t = s - 1;
        float acc = b_val[d];
        const float4* vrow = (const float4*)(values + (b * LL + t) * DVAL);
        #pragma unroll
        for (int k4 = 0; k4 < DVAL / 4; k4++) {
            float4 vv = vrow[k4];
            acc += vv.x * W_val[(k4 * 4 + 0) * DD + d];
            acc += vv.y * W_val[(k4 * 4 + 1) * DD + d];
            acc += vv.z * W_val[(k4 * 4 + 2) * DD + d];
            acc += vv.w * W_val[(k4 * 4 + 3) * DD + d];
        }
        float tm = times[b * LL + t];
        float st = tm / timescales[d & 63];
        out = acc + ((d < 64) ? __sinf(st) : __cosf(st));
    }
    g_x[idx] = out;
}

// ---------------- QKV: grid (tiles, 3) ----------------
__global__ __launch_bounds__(256) void qkv_mma_kernel(
    const int* __restrict__ length,
    const float* __restrict__ Wq, const float* __restrict__ bq,
    const float* __restrict__ Wk, const float* __restrict__ bk,
    const float* __restrict__ Wv, const float* __restrict__ bv) {
    int row0 = blockIdx.x * 64;
    int b = row0 >> 10;
    int valid_len = length[b] + 1;
    if ((row0 & (SS - 1)) >= valid_len) return;
    int wi = blockIdx.y;
    const float* W = (wi == 0) ? Wq : (wi == 1) ? Wk : Wv;
    const float* bias = (wi == 0) ? bq : (wi == 1) ? bk : bv;
    float* out = (wi == 0) ? g_q : (wi == 1) ? g_k : g_v;

    extern __shared__ unsigned smemu[];
    int t = threadIdx.x, w = t >> 5, lane = t & 31;
    int g = lane >> 2, tg = lane & 3, mq = w >> 1, nh = w & 1;

    float acc[8][4];
    #pragma unroll
    for (int i = 0; i < 8; i++) acc[i][0] = acc[i][1] = acc[i][2] = acc[i][3] = 0.f;

    gemm_mainloop_cp(acc, smemu, g_x + (size_t)row0 * DD, DD, W, DD, 4,
                     t, mq, nh, g, tg);

    int r0 = row0 + mq * 16 + g, r1 = r0 + 8;
    #pragma unroll
    for (int nt = 0; nt < 8; nt++) {
        int col = nh * 64 + nt * 8 + 2 * tg;
        float2 bi = *(const float2*)&bias[col];
        float2 lo = {acc[nt][0] + bi.x, acc[nt][1] + bi.y};
        float2 hi = {acc[nt][2] + bi.x, acc[nt][3] + bi.y};
        *(float2*)&out[(size_t)r0 * DD + col] = lo;
        *(float2*)&out[(size_t)r1 * DD + col] = hi;
    }
}

// ---------------- flash attention: 64-key chunks, cp.async double-buffered ----------------
__global__ __launch_bounds__(128) void attn_mma_kernel(const int* __restrict__ length) {
    const int qt = blockIdx.x, h = blockIdx.y, b = blockIdx.z;
    int valid_len = length[b] + 1;
    int q0 = qt * 64;
    if (q0 >= valid_len) return;

    __shared__ unsigned Ks[2][64][20];   // [key][d], raw fp32 bits
    __shared__ unsigned Vs[2][64][24];   // [key][d], raw fp32 bits
    __shared__ unsigned Ps[64][68];      // [q][key], raw fp32 bits

    int t = threadIdx.x;
    int w = t >> 5, lane = t & 31;
    int g = lane >> 2, tg = lane & 3;
    int qrow_base = b * SS + q0 + w * 16;

    int key_st = t >> 1, d8 = (t & 1) << 3;
    auto stage = [&](int c, int buf) {
        size_t src = (size_t)(b * SS + c * 64 + key_st) * DD + h * DH + d8;
        const float* kp = g_k + src;
        cp_async16(smem_u32(&Ks[buf][key_st][d8]), kp);
        cp_async16(smem_u32(&Ks[buf][key_st][d8 + 4]), kp + 4);
        const float* vp = g_v + src;
        cp_async16(smem_u32(&Vs[buf][key_st][d8]), vp);
        cp_async16(smem_u32(&Vs[buf][key_st][d8 + 4]), vp + 4);
        CP_COMMIT();
    };

    unsigned qa[2][4];
    #pragma unroll
    for (int ks = 0; ks < 2; ks++) {
        int r_lo = (qrow_base + g) * DD + h * DH + ks * 8 + tg;
        int r_hi = (qrow_base + g + 8) * DD + h * DH + ks * 8 + tg;
        qa[ks][0] = f2tf(g_q[r_lo] * 0.25f);
        qa[ks][1] = f2tf(g_q[r_hi] * 0.25f);
        qa[ks][2] = f2tf(g_q[r_lo + 4] * 0.25f);
        qa[ks][3] = f2tf(g_q[r_hi + 4] * 0.25f);
    }

    float m0 = -1e30f, m1 = -1e30f, l0 = 0.f, l1 = 0.f;
    float oc[2][4];
    #pragma unroll
    for (int i = 0; i < 2; i++)
        #pragma unroll
        for (int j = 0; j < 4; j++) oc[i][j] = 0.f;

    int nch = (valid_len + 63) >> 6;

    stage(0, 0);

    for (int c = 0; c < nch; c++) {
        int bi = c & 1;
        if (c + 1 < nch) {
            stage(c + 1, bi ^ 1);
            CP_WAIT1();
        } else {
            CP_WAIT0();
        }
        __syncthreads();

        // S = Q K^T  (8 n8 key tiles)
        float sc[8][4];
        #pragma unroll
        for (int nt = 0; nt < 8; nt++) {
            sc[nt][0] = sc[nt][1] = sc[nt][2] = sc[nt][3] = 0.f;
            #pragma unroll
            for (int ks = 0; ks < 2; ks++) {
                unsigned b0 = Ks[bi][nt * 8 + g][ks * 8 + tg];
                unsigned b1 = Ks[bi][nt * 8 + g][ks * 8 + tg + 4];
                mma_tf32(sc[nt], qa[ks][0], qa[ks][1], qa[ks][2], qa[ks][3], b0, b1);
            }
        }

        int limit = valid_len - c * 64;
        float rmax0 = -1e30f, rmax1 = -1e30f;
        #pragma unroll
        for (int nt = 0; nt < 8; nt++) {
            int col0 = nt * 8 + 2 * tg;
            int col1 = col0 + 1;
            sc[nt][0] = (col0 < limit) ? sc[nt][0] : -1e30f;
            sc[nt][1] = (col1 < limit) ? sc[nt][1] : -1e30f;
            sc[nt][2] = (col0 < limit) ? sc[nt][2] : -1e30f;
            sc[nt][3] = (col1 < limit) ? sc[nt][3] : -1e30f;
            rmax0 = fmaxf(rmax0, fmaxf(sc[nt][0], sc[nt][1]));
            rmax1 = fmaxf(rmax1, fmaxf(sc[nt][2], sc[nt][3]));
        }
        rmax0 = fmaxf(rmax0, __shfl_xor_sync(0xffffffff, rmax0, 1));
        rmax0 = fmaxf(rmax0, __shfl_xor_sync(0xffffffff, rmax0, 2));
        rmax1 = fmaxf(rmax1, __shfl_xor_sync(0xffffffff, rmax1, 1));
        rmax1 = fmaxf(rmax1, __shfl_xor_sync(0xffffffff, rmax1, 2));

        float mn0 = fmaxf(m0, rmax0), mn1 = fmaxf(m1, rmax1);
        float scale0 = __expf(m0 - mn0), scale1 = __expf(m1 - mn1);

        float ls0 = 0.f, ls1 = 0.f;
        #pragma unroll
        for (int nt = 0; nt < 8; nt++) {
            float p0 = __expf(sc[nt][0] - mn0);
            float p1 = __expf(sc[nt][1] - mn0);
            float p2 = __expf(sc[nt][2] - mn1);
            float p3 = __expf(sc[nt][3] - mn1);
            ls0 += p0 + p1;
            ls1 += p2 + p3;
            int colw = nt * 8 + 2 * tg;
            uint2 lo = {__float_as_uint(p0), __float_as_uint(p1)};
            uint2 hi = {__float_as_uint(p2), __float_as_uint(p3)};
            *(uint2*)&Ps[w * 16 + g][colw] = lo;
            *(uint2*)&Ps[w * 16 + g + 8][colw] = hi;
        }
        ls0 += __shfl_xor_sync(0xffffffff, ls0, 1);
        ls0 += __shfl_xor_sync(0xffffffff, ls0, 2);
        ls1 += __shfl_xor_sync(0xffffffff, ls1, 1);
        ls1 += __shfl_xor_sync(0xffffffff, ls1, 2);
        l0 = l0 * scale0 + ls0;
        l1 = l1 * scale1 + ls1;
        #pragma unroll
        for (int mt = 0; mt < 2; mt++) {
            oc[mt][0] *= scale0; oc[mt][1] *= scale0;
            oc[mt][2] *= scale1; oc[mt][3] *= scale1;
        }
        m0 = mn0; m1 = mn1;
        __syncwarp();

        // O += P V  (8 k8 steps over 64 keys, 2 n8 d tiles)
        #pragma unroll
        for (int j = 0; j < 8; j++) {
            unsigned pa0 = Ps[w * 16 + g][j * 8 + tg];
            unsigned pa1 = Ps[w * 16 + g + 8][j * 8 + tg];
            unsigned pa2 = Ps[w * 16 + g][j * 8 + tg + 4];
            unsigned pa3 = Ps[w * 16 + g + 8][j * 8 + tg + 4];
            #pragma unroll
            for (int mt = 0; mt < 2; mt++) {
                unsigned vb0 = Vs[bi][j * 8 + tg][mt * 8 + g];
                unsigned vb1 = Vs[bi][j * 8 + tg + 4][mt * 8 + g];
                mma_tf32(oc[mt], pa0, pa1, pa2, pa3, vb0, vb1);
            }
        }
        __syncthreads();
    }

    float inv0 = 1.f / l0, inv1 = 1.f / l1;
    #pragma unroll
    for (int mt = 0; mt < 2; mt++) {
        int col = h * DH + mt * 8 + 2 * tg;
        float2 lo = {oc[mt][0] * inv0, oc[mt][1] * inv0};
        float2 hi = {oc[mt][2] * inv1, oc[mt][3] * inv1};
        *(float2*)&g_o[(qrow_base + g) * DD + col] = lo;
        *(float2*)&g_o[(qrow_base + g + 8) * DD + col] = hi;
    }
}

// ---------------- O-proj + residual + LN1 ----------------
__global__ __launch_bounds__(256) void oproj_ln_mma_kernel(
    const int* __restrict__ length,
    const float* __restrict__ Wo, const float* __restrict__ bo,
    const float* __restrict__ g1, const float* __restrict__ be1) {
    int row0 = blockIdx.x * 64;
    int b = row0 >> 10;
    int valid_len = length[b] + 1;
    if ((row0 & (SS - 1)) >= valid_len) return;

    extern __shared__ unsigned smemu[];
    __shared__ float redS[2][64];
    __shared__ float redQ[2][64];
    int t = threadIdx.x, w = t >> 5, lane = t & 31;
    int g = lane >> 2, tg = lane & 3, mq = w >> 1, nh = w & 1;

    float acc[8][4];
    #pragma unroll
    for (int i = 0; i < 8; i++) acc[i][0] = acc[i][1] = acc[i][2] = acc[i][3] = 0.f;

    gemm_mainloop_cp(acc, smemu, g_o + (size_t)row0 * DD, DD, Wo, DD, 4,
                     t, mq, nh, g, tg);

    int r0 = row0 + mq * 16 + g, r1 = r0 + 8;
    float rs0 = 0.f, rq0 = 0.f, rs1 = 0.f, rq1 = 0.f;
    #pragma unroll
    for (int nt = 0; nt < 8; nt++) {
        int col = nh * 64 + nt * 8 + 2 * tg;
        float2 bi = *(const float2*)&bo[col];
        float2 e0 = *(const float2*)&g_x[(size_t)r0 * DD + col];
        float2 e1 = *(const float2*)&g_x[(size_t)r1 * DD + col];
        acc[nt][0] += bi.x + e0.x;
        acc[nt][1] += bi.y + e0.y;
        acc[nt][2] += bi.x + e1.x;
        acc[nt][3] += bi.y + e1.y;
        rs0 += acc[nt][0] + acc[nt][1];
        rq0 += acc[nt][0] * acc[nt][0] + acc[nt][1] * acc[nt][1];
        rs1 += acc[nt][2] + acc[nt][3];
        rq1 += acc[nt][2] * acc[nt][2] + acc[nt][3] * acc[nt][3];
    }
    rs0 += __shfl_xor_sync(0xffffffff, rs0, 1);
    rs0 += __shfl_xor_sync(0xffffffff, rs0, 2);
    rq0 += __shfl_xor_sync(0xffffffff, rq0, 1);
    rq0 += __shfl_xor_sync(0xffffffff, rq0, 2);
    rs1 += __shfl_xor_sync(0xffffffff, rs1, 1);
    rs1 += __shfl_xor_sync(0xffffffff, rs1, 2);
    rq1 += __shfl_xor_sync(0xffffffff, rq1, 1);
    rq1 += __shfl_xor_sync(0xffffffff, rq1, 2);
    if (tg == 0) {
        redS[nh][mq * 16 + g] = rs0;
        redS[nh][mq * 16 + g + 8] = rs1;
        redQ[nh][mq * 16 + g] = rq0;
        redQ[nh][mq * 16 + g + 8] = rq1;
    }
    __syncthreads();
    float mu0 = (redS[0][mq * 16 + g] + redS[1][mq * 16 + g]) * (1.f / DD);
    float mu1 = (redS[0][mq * 16 + g + 8] + redS[1][mq * 16 + g + 8]) * (1.f / DD);
    float v0 = fmaxf((redQ[0][mq * 16 + g] + redQ[1][mq * 16 + g]) * (1.f / DD) - mu0 * mu0, 0.f);
    float v1 = fmaxf((redQ[0][mq * 16 + g + 8] + redQ[1][mq * 16 + g + 8]) * (1.f / DD) - mu1 * mu1, 0.f);
    float rst0 = rsqrtf(v0 + 1e-3f), rst1 = rsqrtf(v1 + 1e-3f);
    #pragma unroll
    for (int nt = 0; nt < 8; nt++) {
        int col = nh * 64 + nt * 8 + 2 * tg;
        float2 gm = *(const float2*)&g1[col];
        float2 bt = *(const float2*)&be1[col];
        float2 lo = {(acc[nt][0] - mu0) * rst0 * gm.x + bt.x,
                     (acc[nt][1] - mu0) * rst0 * gm.y + bt.y};
        float2 hi = {(acc[nt][2] - mu1) * rst1 * gm.x + bt.x,
                     (acc[nt][3] - mu1) * rst1 * gm.y + bt.y};
        *(float2*)&g_x[(size_t)r0 * DD + col] = lo;
        *(float2*)&g_x[(size_t)r1 * DD + col] = hi;
    }
}

// ---------------- FFN1: grid (tiles, 4) ----------------
__global__ __launch_bounds__(256) void ffn1_mma_kernel(
    const int* __restrict__ length,
    const float* __restrict__ W1, const float* __restrict__ b1) {
    int row0 = blockIdx.x * 64;
    int b = row0 >> 10;
    int valid_len = length[b] + 1;
    if ((row0 & (SS - 1)) >= valid_len) return;
    int ncol0 = blockIdx.y * 128;

    extern __shared__ unsigned smemu[];
    int t = threadIdx.x, w = t >> 5, lane = t & 31;
    int g = lane >> 2, tg = lane & 3, mq = w >> 1, nh = w & 1;

    float acc[8][4];
    #pragma unroll
    for (int i = 0; i < 8; i++) acc[i][0] = acc[i][1] = acc[i][2] = acc[i][3] = 0.f;

    gemm_mainloop_cp(acc, smemu, g_x + (size_t)row0 * DD, DD, W1 + ncol0, DFF, 4,
                     t, mq, nh, g, tg);

    int r0 = row0 + mq * 16 + g, r1 = r0 + 8;
    #pragma unroll
    for (int nt = 0; nt < 8; nt++) {
        int col = ncol0 + nh * 64 + nt * 8 + 2 * tg;
        float2 bi = *(const float2*)&b1[col];
        float2 lo = {fmaxf(acc[nt][0] + bi.x, 0.f), fmaxf(acc[nt][1] + bi.y, 0.f)};
        float2 hi = {fmaxf(acc[nt][2] + bi.x, 0.f), fmaxf(acc[nt][3] + bi.y, 0.f)};
        *(float2*)&g_h[(size_t)r0 * DFF + col] = lo;
        *(float2*)&g_h[(size_t)r1 * DFF + col] = hi;
    }
}

// ---------------- FFN2 + residual + LN2 ----------------
__global__ __launch_bounds__(256) void ffn2_ln_mma_kernel(
    const int* __restrict__ length,
    const float* __restrict__ W2, const float* __restrict__ b2,
    const float* __restrict__ g2, const float* __restrict__ be2) {
    int row0 = blockIdx.x * 64;
    int b = row0 >> 10;
    int valid_len = length[b] + 1;
    if ((row0 & (SS - 1)) >= valid_len) return;

    extern __shared__ unsigned smemu[];
    __shared__ float redS[2][64];
    __shared__ float redQ[2][64];
    int t = threadIdx.x, w = t >> 5, lane = t & 31;
    int g = lane >> 2, tg = lane & 3, mq = w >> 1, nh = w & 1;

    float acc[8][4];
    #pragma unroll
    for (int i = 0; i < 8; i++) acc[i][0] = acc[i][1] = acc[i][2] = acc[i][3] = 0.f;

    gemm_mainloop_cp(acc, smemu, g_h + (size_t)row0 * DFF, DFF, W2, DD, DFF / 32,
                     t, mq, nh, g, tg);

    int r0 = row0 + mq * 16 + g, r1 = r0 + 8;
    float rs0 = 0.f, rq0 = 0.f, rs1 = 0.f, rq1 = 0.f;
    #pragma unroll
    for (int nt = 0; nt < 8; nt++) {
        int col = nh * 64 + nt * 8 + 2 * tg;
        float2 bi = *(const float2*)&b2[col];
        float2 e0 = *(const float2*)&g_x[(size_t)r0 * DD + col];
        float2 e1 = *(const float2*)&g_x[(size_t)r1 * DD + col];
        acc[nt][0] += bi.x + e0.x;
        acc[nt][1] += bi.y + e0.y;
        acc[nt][2] += bi.x + e1.x;
        acc[nt][3] += bi.y + e1.y;
        rs0 += acc[nt][0] + acc[nt][1];
        rq0 += acc[nt][0] * acc[nt][0] + acc[nt][1] * acc[nt][1];
        rs1 += acc[nt][2] + acc[nt][3];
        rq1 += acc[nt][2] * acc[nt][2] + acc[nt][3] * acc[nt][3];
    }
    rs0 += __shfl_xor_sync(0xffffffff, rs0, 1);
    rs0 += __shfl_xor_sync(0xffffffff, rs0, 2);
    rq0 += __shfl_xor_sync(0xffffffff, rq0, 1);
    rq0 += __shfl_xor_sync(0xffffffff, rq0, 2);
    rs1 += __shfl_xor_sync(0xffffffff, rs1, 1);
    rs1 += __shfl_xor_sync(0xffffffff, rs1, 2);
    rq1 += __shfl_xor_sync(0xffffffff, rq1, 1);
    rq1 += __shfl_xor_sync(0xffffffff, rq1, 2);
    if (tg == 0) {
        redS[nh][mq * 16 + g] = rs0;
        redS[nh][mq * 16 + g + 8] = rs1;
        redQ[nh][mq * 16 + g] = rq0;
        redQ[nh][mq * 16 + g + 8] = rq1;
    }
    __syncthreads();
    float mu0 = (redS[0][mq * 16 + g] + redS[1][mq * 16 + g]) * (1.f / DD);
    float mu1 = (redS[0][mq * 16 + g + 8] + redS[1][mq * 16 + g + 8]) * (1.f / DD);
    float v0 = fmaxf((redQ[0][mq * 16 + g] + redQ[1][mq * 16 + g]) * (1.f / DD) - mu0 * mu0, 0.f);
    float v1 = fmaxf((redQ[0][mq * 16 + g + 8] + redQ[1][mq * 16 + g + 8]) * (1.f / DD) - mu1 * mu1, 0.f);
    float rst0 = rsqrtf(v0 + 1e-3f), rst1 = rsqrtf(v1 + 1e-3f);
    #pragma unroll
    for (int nt = 0; nt < 8; nt++) {
        int col = nh * 64 + nt * 8 + 2 * tg;
        float2 gm = *(const float2*)&g2[col];
        float2 bt = *(const float2*)&be2[col];
        float2 lo = {(acc[nt][0] - mu0) * rst0 * gm.x + bt.x,
                     (acc[nt][1] - mu0) * rst0 * gm.y + bt.y};
        float2 hi = {(acc[nt][2] - mu1) * rst1 * gm.x + bt.x,
                     (acc[nt][3] - mu1) * rst1 * gm.y + bt.y};
        *(float2*)&g_x[(size_t)r0 * DD + col] = lo;
        *(float2*)&g_x[(size_t)r1 * DD + col] = hi;
    }
}

// ---------------- masked mean-pool + MLP head + sigmoid ----------------
__global__ __launch_bounds__(256) void head_kernel(
    const int* __restrict__ length,
    const float* __restrict__ Wm1, const float* __restrict__ bm1,
    const float* __restrict__ Wm2, const float* __restrict__ bm2,
    float* __restrict__ out) {
    int b = blockIdx.x;
    int t = threadIdx.x;
    __shared__ float part[2][DD];
    __shared__ float agg[DD];
    __shared__ float hh[MLPH];
    __shared__ float red[8];
    int cnt = length[b] + 1;
    int d = t & 127, grp = t >> 7;
    float s0 = 0.f, s1 = 0.f, s2 = 0.f, s3 = 0.f;
    int ss = grp;
    for (; ss + 6 < cnt; ss += 8) {
        s0 += g_x[(b * SS + ss) * DD + d];
        s1 += g_x[(b * SS + ss + 2) * DD + d];
        s2 += g_x[(b * SS + ss + 4) * DD + d];
        s3 += g_x[(b * SS + ss + 6) * DD + d];
    }
    for (; ss < cnt; ss += 2) s0 += g_x[(b * SS + ss) * DD + d];
    part[grp][d] = s0 + s1 + s2 + s3;
    __syncthreads();
    if (t < DD) agg[t] = (part[0][t] + part[1][t]) / (float)cnt;
    __syncthreads();
    {
        float acc = bm1[t];
        #pragma unroll 8
        for (int k = 0; k < DD; k++) acc += agg[k] * Wm1[k * MLPH + t];
        hh[t] = fmaxf(acc, 0.f);
    }
    __syncthreads();
    float v = hh[t] * Wm2[t];
    #pragma unroll
    for (int o = 16; o > 0; o >>= 1) v += __shfl_xor_sync(0xffffffff, v, o);
    if ((t & 31) == 0) red[t >> 5] = v;
    __syncthreads();
    if (t == 0) {
        float s = 0.f;
        #pragma unroll
        for (int i = 0; i < 8; i++) s += red[i];
        s += bm2[0];
        out[b] = 1.f / (1.f + __expf(-s));
    }
}

// ---------------- launch ----------------
extern "C" void kernel_launch(void* const* d_in, const int* in_sizes, int n_in,
                              void* d_out, int out_size) {
    (void)in_sizes; (void)n_in; (void)out_size;
    const float* demo       = (const float*)d_in[0];
    const float* times      = (const float*)d_in[1];
    const float* values     = (const float*)d_in[2];
    const int*   length     = (const int*)d_in[3];
    const float* timescales = (const float*)d_in[4];
    const float* W_demo = (const float*)d_in[5];
    const float* b_demo = (const float*)d_in[6];
    const float* W_val  = (const float*)d_in[7];
    const float* b_val  = (const float*)d_in[8];
    const float* Wq = (const float*)d_in[9];
    const float* bq = (const float*)d_in[10];
    const float* Wk = (const float*)d_in[11];
    const float* bk = (const float*)d_in[12];
    const float* Wv = (const float*)d_in[13];
    const float* bv = (const float*)d_in[14];
    const float* Wo = (const float*)d_in[15];
    const float* bo = (const float*)d_in[16];
    const float* ln1g = (const float*)d_in[17];
    const float* ln1b = (const float*)d_in[18];
    const float* W1 = (const float*)d_in[19];
    const float* b1 = (const float*)d_in[20];
    const float* W2 = (const float*)d_in[21];
    const float* b2 = (const float*)d_in[22];
    const float* ln2g = (const float*)d_in[23];
    const float* ln2b = (const float*)d_in[24];
    const float* Wm1 = (const float*)d_in[25];
    const float* bm1 = (const float*)d_in[26];
    const float* Wm2 = (const float*)d_in[27];
    const float* bm2 = (const float*)d_in[28];
    float* out = (float*)d_out;

    cudaFuncSetAttribute(qkv_mma_kernel, cudaFuncAttributeMaxDynamicSharedMemorySize, GEMM_SMEM_BYTES);
    cudaFuncSetAttribute(oproj_ln_mma_kernel, cudaFuncAttributeMaxDynamicSharedMemorySize, GEMM_SMEM_BYTES);
    cudaFuncSetAttribute(ffn1_mma_kernel, cudaFuncAttributeMaxDynamicSharedMemorySize, GEMM_SMEM_BYTES);
    cudaFuncSetAttribute(ffn2_ln_mma_kernel, cudaFuncAttributeMaxDynamicSharedMemorySize, GEMM_SMEM_BYTES);

    embed_kernel<<<(BB * SS * DD + 255) / 256, 256>>>(
        demo, times, values, timescales, W_demo, b_demo, W_val, b_val, length);

    int ntiles = BB * SS / 64;
    for (int l = 0; l < NLAY; l++) {
        dim3 gq(ntiles, 3);
        qkv_mma_kernel<<<gq, 256, GEMM_SMEM_BYTES>>>(length,
            Wq + l * DD * DD, bq + l * DD,
            Wk + l * DD * DD, bk + l * DD,
            Wv + l * DD * DD, bv + l * DD);
        dim3 ag(SS / 64, HH, BB);
        attn_mma_kernel<<<ag, 128>>>(length);
        oproj_ln_mma_kernel<<<ntiles, 256, GEMM_SMEM_BYTES>>>(length,
            Wo + l * DD * DD, bo + l * DD, ln1g + l * DD, ln1b + l * DD);
        dim3 gf(ntiles, 4);
        ffn1_mma_kernel<<<gf, 256, GEMM_SMEM_BYTES>>>(length, W1 + l * DD * DFF, b1 + l * DFF);
        ffn2_ln_mma_kernel<<<ntiles, 256, GEMM_SMEM_BYTES>>>(length,
            W2 + l * DFF * DD, b2 + l * DD, ln2g + l * DD, ln2b + l * DD);
    }

    head_kernel<<<BB, 256>>>(length, Wm1, bm1, Wm2, bm2, out);
}

// round 10
// speedup vs baseline: 1.1566x; 1.0352x over previous
#include <cuda_runtime.h>
#include <math.h>

#define BB 16
#define LL 1023
#define SS 1024
#define DD 128
#define DVAL 64
#define NDEMO 16
#define HH 8
#define DH 16
#define NLAY 2
#define DFF 512
#define MLPH 256

#define AS_ELEMS (64 * 36)
#define BS_ELEMS (32 * 136)
#define STAGE_ELEMS (AS_ELEMS + BS_ELEMS)
#define GEMM_SMEM_BYTES (3 * STAGE_ELEMS * 4)

// ---------------- device scratch (no allocs allowed) ----------------
__device__ float g_x[BB * SS * DD];
__device__ float g_q[BB * SS * DD];
__device__ float g_k[BB * SS * DD];
__device__ float g_v[BB * SS * DD];
__device__ float g_o[BB * SS * DD];
__device__ float g_h[BB * SS * DFF];

__device__ __forceinline__ unsigned f2tf(float x) {
    unsigned r;
    asm("cvt.rna.tf32.f32 %0, %1;" : "=r"(r) : "f"(x));
    return r;
}

__device__ __forceinline__ float ex2f(float x) {
    float r;
    asm("ex2.approx.ftz.f32 %0, %1;" : "=f"(r) : "f"(x));
    return r;
}

__device__ __forceinline__ void mma_tf32(float* c, unsigned a0, unsigned a1,
                                         unsigned a2, unsigned a3,
                                         unsigned b0, unsigned b1) {
    asm("mma.sync.aligned.m16n8k8.row.col.f32.tf32.tf32.f32 "
        "{%0,%1,%2,%3},{%4,%5,%6,%7},{%8,%9},{%0,%1,%2,%3};"
        : "+f"(c[0]), "+f"(c[1]), "+f"(c[2]), "+f"(c[3])
        : "r"(a0), "r"(a1), "r"(a2), "r"(a3), "r"(b0), "r"(b1));
}

__device__ __forceinline__ unsigned smem_u32(const void* p) {
    return (unsigned)__cvta_generic_to_shared(p);
}

__device__ __forceinline__ void cp_async16(unsigned s, const void* g) {
    asm volatile("cp.async.ca.shared.global [%0], [%1], 16;" :: "r"(s), "l"(g));
}
#define CP_COMMIT() asm volatile("cp.async.commit_group;" ::: "memory")
#define CP_WAIT2() asm volatile("cp.async.wait_group 2;" ::: "memory")
#define CP_WAIT1() asm volatile("cp.async.wait_group 1;" ::: "memory")
#define CP_WAIT0() asm volatile("cp.async.wait_group 0;" ::: "memory")

// ---------------- GEMM tile: 64 rows x 128 cols, 256 threads ----------------
__device__ __forceinline__ void compute_chunk(float (*acc)[4],
                                              const unsigned (*As)[36],
                                              const unsigned (*Bs)[136],
                                              int mq, int nh, int g, int tg) {
    int mr = mq * 16;
    #pragma unroll
    for (int ks = 0; ks < 4; ks++) {
        unsigned a0 = As[mr + g][ks * 8 + tg];
        unsigned a1 = As[mr + g + 8][ks * 8 + tg];
        unsigned a2 = As[mr + g][ks * 8 + tg + 4];
        unsigned a3 = As[mr + g + 8][ks * 8 + tg + 4];
        #pragma unroll
        for (int nt = 0; nt < 8; nt++) {
            unsigned b0 = Bs[ks * 8 + tg][nh * 64 + nt * 8 + g];
            unsigned b1 = Bs[ks * 8 + tg + 4][nh * 64 + nt * 8 + g];
            mma_tf32(acc[nt], a0, a1, a2, a3, b0, b1);
        }
    }
}

// cp.async triple-buffered (depth-2) GEMM mainloop over nK k-chunks of 32.
__device__ __forceinline__ void gemm_mainloop_cp(
    float (*acc)[4], unsigned* smemu,
    const float* Ag, int lda, const float* Wg, int ldw, int nK,
    int t, int mq, int nh, int g, int tg) {
    int ra = t >> 2, c0 = (t & 3) * 8;
    int rb = t >> 3, f0 = t & 7;

    auto stage = [&](int kc) {
        unsigned* base = smemu + (kc % 3) * STAGE_ELEMS;
        unsigned (*As)[36] = (unsigned(*)[36])base;
        unsigned (*Bs)[136] = (unsigned(*)[136])(base + AS_ELEMS);
        const float* ap = Ag + (size_t)ra * lda + kc * 32 + c0;
        cp_async16(smem_u32(&As[ra][c0]), ap);
        cp_async16(smem_u32(&As[ra][c0 + 4]), ap + 4);
        const float* bp = Wg + (size_t)(kc * 32 + rb) * ldw;
        #pragma unroll
        for (int j = 0; j < 4; j++) {
            int c = (f0 + j * 8) * 4;
            cp_async16(smem_u32(&Bs[rb][c]), bp + c);
        }
        CP_COMMIT();
    };

    stage(0);
    if (nK > 1) stage(1);
    for (int kc = 0; kc < nK; kc++) {
        if (kc + 2 < nK) {
            stage(kc + 2);
            CP_WAIT2();
        } else if (kc + 1 < nK) {
            CP_WAIT1();
        } else {
            CP_WAIT0();
        }
        __syncthreads();
        unsigned* base = smemu + (kc % 3) * STAGE_ELEMS;
        compute_chunk(acc, (const unsigned(*)[36])base,
                      (const unsigned(*)[136])(base + AS_ELEMS), mq, nh, g, tg);
        __syncthreads();
    }
}

// ---------------- embedding ----------------
__global__ __launch_bounds__(256) void embed_kernel(
    const float* __restrict__ demo, const float* __restrict__ times,
    const float* __restrict__ values, const float* __restrict__ timescales,
    const float* __restrict__ W_demo, const float* __restrict__ b_demo,
    const float* __restrict__ W_val, const float* __restrict__ b_val,
    const int* __restrict__ length) {
    int idx = blockIdx.x * blockDim.x + threadIdx.x;
    if (idx >= BB * SS * DD) return;
    int d = idx % DD;
    int s = (idx / DD) % SS;
    int b = idx / (DD * SS);
    if (s > length[b]) return;
    float out;
    if (s == 0) {
        float acc = b_demo[d];
        #pragma unroll
        for (int k = 0; k < NDEMO; k++) acc += demo[b * NDEMO + k] * W_demo[k * DD + d];
        out = acc;
    } else {
        int t = s - 1;
        float acc = b_val[d];
        const float4* vrow = (const float4*)(values + (b * LL + t) * DVAL);
        #pragma unroll
        for (int k4 = 0; k4 < DVAL / 4; k4++) {
            float4 vv = vrow[k4];
            acc += vv.x * W_val[(k4 * 4 + 0) * DD + d];
            acc += vv.y * W_val[(k4 * 4 + 1) * DD + d];
            acc += vv.z * W_val[(k4 * 4 + 2) * DD + d];
            acc += vv.w * W_val[(k4 * 4 + 3) * DD + d];
        }
        float tm = times[b * LL + t];
        float st = tm / timescales[d & 63];
        out = acc + ((d < 64) ? __sinf(st) : __cosf(st));
    }
    g_x[idx] = out;
}

// ---------------- QKV: grid (tiles, 3) ----------------
__global__ __launch_bounds__(256) void qkv_mma_kernel(
    const int* __restrict__ length,
    const float* __restrict__ Wq, const float* __restrict__ bq,
    const float* __restrict__ Wk, const float* __restrict__ bk,
    const float* __restrict__ Wv, const float* __restrict__ bv) {
    int row0 = blockIdx.x * 64;
    int b = row0 >> 10;
    int valid_len = length[b] + 1;
    if ((row0 & (SS - 1)) >= valid_len) return;
    int wi = blockIdx.y;
    const float* W = (wi == 0) ? Wq : (wi == 1) ? Wk : Wv;
    const float* bias = (wi == 0) ? bq : (wi == 1) ? bk : bv;
    float* out = (wi == 0) ? g_q : (wi == 1) ? g_k : g_v;

    extern __shared__ unsigned smemu[];
    int t = threadIdx.x, w = t >> 5, lane = t & 31;
    int g = lane >> 2, tg = lane & 3, mq = w >> 1, nh = w & 1;

    float acc[8][4];
    #pragma unroll
    for (int i = 0; i < 8; i++) acc[i][0] = acc[i][1] = acc[i][2] = acc[i][3] = 0.f;

    gemm_mainloop_cp(acc, smemu, g_x + (size_t)row0 * DD, DD, W, DD, 4,
                     t, mq, nh, g, tg);

    int r0 = row0 + mq * 16 + g, r1 = r0 + 8;
    #pragma unroll
    for (int nt = 0; nt < 8; nt++) {
        int col = nh * 64 + nt * 8 + 2 * tg;
        float2 bi = *(const float2*)&bias[col];
        float2 lo = {acc[nt][0] + bi.x, acc[nt][1] + bi.y};
        float2 hi = {acc[nt][2] + bi.x, acc[nt][3] + bi.y};
        *(float2*)&out[(size_t)r0 * DD + col] = lo;
        *(float2*)&out[(size_t)r1 * DD + col] = hi;
    }
}

// ---------------- flash attention: no-max softmax (scores provably small) ----------------
__global__ __launch_bounds__(128) void attn_mma_kernel(const int* __restrict__ length) {
    const int qt = blockIdx.x, h = blockIdx.y, b = blockIdx.z;
    int valid_len = length[b] + 1;
    int q0 = qt * 64;
    if (q0 >= valid_len) return;

    __shared__ unsigned Ks[2][64][20];   // [key][d], raw fp32 bits
    __shared__ unsigned Vs[2][64][24];   // [key][d], raw fp32 bits
    __shared__ unsigned Ps[64][68];      // [q][key], raw fp32 bits

    int t = threadIdx.x;
    int w = t >> 5, lane = t & 31;
    int g = lane >> 2, tg = lane & 3;
    int qrow_base = b * SS + q0 + w * 16;

    int key_st = t >> 1, d8 = (t & 1) << 3;
    auto stage = [&](int c, int buf) {
        size_t src = (size_t)(b * SS + c * 64 + key_st) * DD + h * DH + d8;
        const float* kp = g_k + src;
        cp_async16(smem_u32(&Ks[buf][key_st][d8]), kp);
        cp_async16(smem_u32(&Ks[buf][key_st][d8 + 4]), kp + 4);
        const float* vp = g_v + src;
        cp_async16(smem_u32(&Vs[buf][key_st][d8]), vp);
        cp_async16(smem_u32(&Vs[buf][key_st][d8 + 4]), vp + 4);
        CP_COMMIT();
    };

    // Q fragments with 1/sqrt(dh) * log2(e) folded in (scores -> exp2 domain)
    const float qscale = 0.25f * 1.44269504f;
    unsigned qa[2][4];
    #pragma unroll
    for (int ks = 0; ks < 2; ks++) {
        int r_lo = (qrow_base + g) * DD + h * DH + ks * 8 + tg;
        int r_hi = (qrow_base + g + 8) * DD + h * DH + ks * 8 + tg;
        qa[ks][0] = f2tf(g_q[r_lo] * qscale);
        qa[ks][1] = f2tf(g_q[r_hi] * qscale);
        qa[ks][2] = f2tf(g_q[r_lo + 4] * qscale);
        qa[ks][3] = f2tf(g_q[r_hi + 4] * qscale);
    }

    float l0 = 0.f, l1 = 0.f;
    float oc[2][4];
    #pragma unroll
    for (int i = 0; i < 2; i++)
        #pragma unroll
        for (int j = 0; j < 4; j++) oc[i][j] = 0.f;

    int nch = (valid_len + 63) >> 6;

    stage(0, 0);

    for (int c = 0; c < nch; c++) {
        int bi = c & 1;
        if (c + 1 < nch) {
            stage(c + 1, bi ^ 1);
            CP_WAIT1();
        } else {
            CP_WAIT0();
        }
        __syncthreads();

        // S = Q K^T  (8 n8 key tiles), already in log2 domain
        float sc[8][4];
        #pragma unroll
        for (int nt = 0; nt < 8; nt++) {
            sc[nt][0] = sc[nt][1] = sc[nt][2] = sc[nt][3] = 0.f;
            #pragma unroll
            for (int ks = 0; ks < 2; ks++) {
                unsigned b0 = Ks[bi][nt * 8 + g][ks * 8 + tg];
                unsigned b1 = Ks[bi][nt * 8 + g][ks * 8 + tg + 4];
                mma_tf32(sc[nt], qa[ks][0], qa[ks][1], qa[ks][2], qa[ks][3], b0, b1);
            }
        }

        int limit = valid_len - c * 64;
        #pragma unroll
        for (int nt = 0; nt < 8; nt++) {
            int col0 = nt * 8 + 2 * tg;
            int col1 = col0 + 1;
            float p0 = ex2f((col0 < limit) ? sc[nt][0] : -1e30f);
            float p1 = ex2f((col1 < limit) ? sc[nt][1] : -1e30f);
            float p2 = ex2f((col0 < limit) ? sc[nt][2] : -1e30f);
            float p3 = ex2f((col1 < limit) ? sc[nt][3] : -1e30f);
            l0 += p0 + p1;
            l1 += p2 + p3;
            int colw = nt * 8 + 2 * tg;
            uint2 lo = {__float_as_uint(p0), __float_as_uint(p1)};
            uint2 hi = {__float_as_uint(p2), __float_as_uint(p3)};
            *(uint2*)&Ps[w * 16 + g][colw] = lo;
            *(uint2*)&Ps[w * 16 + g + 8][colw] = hi;
        }
        __syncwarp();

        // O += P V  (8 k8 steps over 64 keys, 2 n8 d tiles)
        #pragma unroll
        for (int j = 0; j < 8; j++) {
            unsigned pa0 = Ps[w * 16 + g][j * 8 + tg];
            unsigned pa1 = Ps[w * 16 + g + 8][j * 8 + tg];
            unsigned pa2 = Ps[w * 16 + g][j * 8 + tg + 4];
            unsigned pa3 = Ps[w * 16 + g + 8][j * 8 + tg + 4];
            #pragma unroll
            for (int mt = 0; mt < 2; mt++) {
                unsigned vb0 = Vs[bi][j * 8 + tg][mt * 8 + g];
                unsigned vb1 = Vs[bi][j * 8 + tg + 4][mt * 8 + g];
                mma_tf32(oc[mt], pa0, pa1, pa2, pa3, vb0, vb1);
            }
        }
        __syncthreads();
    }

    // row sums across the 4-lane groups
    l0 += __shfl_xor_sync(0xffffffff, l0, 1);
    l0 += __shfl_xor_sync(0xffffffff, l0, 2);
    l1 += __shfl_xor_sync(0xffffffff, l1, 1);
    l1 += __shfl_xor_sync(0xffffffff, l1, 2);

    float inv0 = 1.f / l0, inv1 = 1.f / l1;
    #pragma unroll
    for (int mt = 0; mt < 2; mt++) {
        int col = h * DH + mt * 8 + 2 * tg;
        float2 lo = {oc[mt][0] * inv0, oc[mt][1] * inv0};
        float2 hi = {oc[mt][2] * inv1, oc[mt][3] * inv1};
        *(float2*)&g_o[(qrow_base + g) * DD + col] = lo;
        *(float2*)&g_o[(qrow_base + g + 8) * DD + col] = hi;
    }
}

// ---------------- O-proj + residual + LN1 ----------------
__global__ __launch_bounds__(256) void oproj_ln_mma_kernel(
    const int* __restrict__ length,
    const float* __restrict__ Wo, const float* __restrict__ bo,
    const float* __restrict__ g1, const float* __restrict__ be1) {
    int row0 = blockIdx.x * 64;
    int b = row0 >> 10;
    int valid_len = length[b] + 1;
    if ((row0 & (SS - 1)) >= valid_len) return;

    extern __shared__ unsigned smemu[];
    __shared__ float redS[2][64];
    __shared__ float redQ[2][64];
    int t = threadIdx.x, w = t >> 5, lane = t & 31;
    int g = lane >> 2, tg = lane & 3, mq = w >> 1, nh = w & 1;

    float acc[8][4];
    #pragma unroll
    for (int i = 0; i < 8; i++) acc[i][0] = acc[i][1] = acc[i][2] = acc[i][3] = 0.f;

    gemm_mainloop_cp(acc, smemu, g_o + (size_t)row0 * DD, DD, Wo, DD, 4,
                     t, mq, nh, g, tg);

    int r0 = row0 + mq * 16 + g, r1 = r0 + 8;
    float rs0 = 0.f, rq0 = 0.f, rs1 = 0.f, rq1 = 0.f;
    #pragma unroll
    for (int nt = 0; nt < 8; nt++) {
        int col = nh * 64 + nt * 8 + 2 * tg;
        float2 bi = *(const float2*)&bo[col];
        float2 e0 = *(const float2*)&g_x[(size_t)r0 * DD + col];
        float2 e1 = *(const float2*)&g_x[(size_t)r1 * DD + col];
        acc[nt][0] += bi.x + e0.x;
        acc[nt][1] += bi.y + e0.y;
        acc[nt][2] += bi.x + e1.x;
        acc[nt][3] += bi.y + e1.y;
        rs0 += acc[nt][0] + acc[nt][1];
        rq0 += acc[nt][0] * acc[nt][0] + acc[nt][1] * acc[nt][1];
        rs1 += acc[nt][2] + acc[nt][3];
        rq1 += acc[nt][2] * acc[nt][2] + acc[nt][3] * acc[nt][3];
    }
    rs0 += __shfl_xor_sync(0xffffffff, rs0, 1);
    rs0 += __shfl_xor_sync(0xffffffff, rs0, 2);
    rq0 += __shfl_xor_sync(0xffffffff, rq0, 1);
    rq0 += __shfl_xor_sync(0xffffffff, rq0, 2);
    rs1 += __shfl_xor_sync(0xffffffff, rs1, 1);
    rs1 += __shfl_xor_sync(0xffffffff, rs1, 2);
    rq1 += __shfl_xor_sync(0xffffffff, rq1, 1);
    rq1 += __shfl_xor_sync(0xffffffff, rq1, 2);
    if (tg == 0) {
        redS[nh][mq * 16 + g] = rs0;
        redS[nh][mq * 16 + g + 8] = rs1;
        redQ[nh][mq * 16 + g] = rq0;
        redQ[nh][mq * 16 + g + 8] = rq1;
    }
    __syncthreads();
    float mu0 = (redS[0][mq * 16 + g] + redS[1][mq * 16 + g]) * (1.f / DD);
    float mu1 = (redS[0][mq * 16 + g + 8] + redS[1][mq * 16 + g + 8]) * (1.f / DD);
    float v0 = fmaxf((redQ[0][mq * 16 + g] + redQ[1][mq * 16 + g]) * (1.f / DD) - mu0 * mu0, 0.f);
    float v1 = fmaxf((redQ[0][mq * 16 + g + 8] + redQ[1][mq * 16 + g + 8]) * (1.f / DD) - mu1 * mu1, 0.f);
    float rst0 = rsqrtf(v0 + 1e-3f), rst1 = rsqrtf(v1 + 1e-3f);
    #pragma unroll
    for (int nt = 0; nt < 8; nt++) {
        int col = nh * 64 + nt * 8 + 2 * tg;
        float2 gm = *(const float2*)&g1[col];
        float2 bt = *(const float2*)&be1[col];
        float2 lo = {(acc[nt][0] - mu0) * rst0 * gm.x + bt.x,
                     (acc[nt][1] - mu0) * rst0 * gm.y + bt.y};
        float2 hi = {(acc[nt][2] - mu1) * rst1 * gm.x + bt.x,
                     (acc[nt][3] - mu1) * rst1 * gm.y + bt.y};
        *(float2*)&g_x[(size_t)r0 * DD + col] = lo;
        *(float2*)&g_x[(size_t)r1 * DD + col] = hi;
    }
}

// ---------------- FFN1: grid (tiles, 4) ----------------
__global__ __launch_bounds__(256) void ffn1_mma_kernel(
    const int* __restrict__ length,
    const float* __restrict__ W1, const float* __restrict__ b1) {
    int row0 = blockIdx.x * 64;
    int b = row0 >> 10;
    int valid_len = length[b] + 1;
    if ((row0 & (SS - 1)) >= valid_len) return;
    int ncol0 = blockIdx.y * 128;

    extern __shared__ unsigned smemu[];
    int t = threadIdx.x, w = t >> 5, lane = t & 31;
    int g = lane >> 2, tg = lane & 3, mq = w >> 1, nh = w & 1;

    float acc[8][4];
    #pragma unroll
    for (int i = 0; i < 8; i++) acc[i][0] = acc[i][1] = acc[i][2] = acc[i][3] = 0.f;

    gemm_mainloop_cp(acc, smemu, g_x + (size_t)row0 * DD, DD, W1 + ncol0, DFF, 4,
                     t, mq, nh, g, tg);

    int r0 = row0 + mq * 16 + g, r1 = r0 + 8;
    #pragma unroll
    for (int nt = 0; nt < 8; nt++) {
        int col = ncol0 + nh * 64 + nt * 8 + 2 * tg;
        float2 bi = *(const float2*)&b1[col];
        float2 lo = {fmaxf(acc[nt][0] + bi.x, 0.f), fmaxf(acc[nt][1] + bi.y, 0.f)};
        float2 hi = {fmaxf(acc[nt][2] + bi.x, 0.f), fmaxf(acc[nt][3] + bi.y, 0.f)};
        *(float2*)&g_h[(size_t)r0 * DFF + col] = lo;
        *(float2*)&g_h[(size_t)r1 * DFF + col] = hi;
    }
}

// ---------------- FFN2 + residual + LN2 ----------------
__global__ __launch_bounds__(256) void ffn2_ln_mma_kernel(
    const int* __restrict__ length,
    const float* __restrict__ W2, const float* __restrict__ b2,
    const float* __restrict__ g2, const float* __restrict__ be2) {
    int row0 = blockIdx.x * 64;
    int b = row0 >> 10;
    int valid_len = length[b] + 1;
    if ((row0 & (SS - 1)) >= valid_len) return;

    extern __shared__ unsigned smemu[];
    __shared__ float redS[2][64];
    __shared__ float redQ[2][64];
    int t = threadIdx.x, w = t >> 5, lane = t & 31;
    int g = lane >> 2, tg = lane & 3, mq = w >> 1, nh = w & 1;

    float acc[8][4];
    #pragma unroll
    for (int i = 0; i < 8; i++) acc[i][0] = acc[i][1] = acc[i][2] = acc[i][3] = 0.f;

    gemm_mainloop_cp(acc, smemu, g_h + (size_t)row0 * DFF, DFF, W2, DD, DFF / 32,
                     t, mq, nh, g, tg);

    int r0 = row0 + mq * 16 + g, r1 = r0 + 8;
    float rs0 = 0.f, rq0 = 0.f, rs1 = 0.f, rq1 = 0.f;
    #pragma unroll
    for (int nt = 0; nt < 8; nt++) {
        int col = nh * 64 + nt * 8 + 2 * tg;
        float2 bi = *(const float2*)&b2[col];
        float2 e0 = *(const float2*)&g_x[(size_t)r0 * DD + col];
        float2 e1 = *(const float2*)&g_x[(size_t)r1 * DD + col];
        acc[nt][0] += bi.x + e0.x;
        acc[nt][1] += bi.y + e0.y;
        acc[nt][2] += bi.x + e1.x;
        acc[nt][3] += bi.y + e1.y;
        rs0 += acc[nt][0] + acc[nt][1];
        rq0 += acc[nt][0] * acc[nt][0] + acc[nt][1] * acc[nt][1];
        rs1 += acc[nt][2] + acc[nt][3];
        rq1 += acc[nt][2] * acc[nt][2] + acc[nt][3] * acc[nt][3];
    }
    rs0 += __shfl_xor_sync(0xffffffff, rs0, 1);
    rs0 += __shfl_xor_sync(0xffffffff, rs0, 2);
    rq0 += __shfl_xor_sync(0xffffffff, rq0, 1);
    rq0 += __shfl_xor_sync(0xffffffff, rq0, 2);
    rs1 += __shfl_xor_sync(0xffffffff, rs1, 1);
    rs1 += __shfl_xor_sync(0xffffffff, rs1, 2);
    rq1 += __shfl_xor_sync(0xffffffff, rq1, 1);
    rq1 += __shfl_xor_sync(0xffffffff, rq1, 2);
    if (tg == 0) {
        redS[nh][mq * 16 + g] = rs0;
        redS[nh][mq * 16 + g + 8] = rs1;
        redQ[nh][mq * 16 + g] = rq0;
        redQ[nh][mq * 16 + g + 8] = rq1;
    }
    __syncthreads();
    float mu0 = (redS[0][mq * 16 + g] + redS[1][mq * 16 + g]) * (1.f / DD);
    float mu1 = (redS[0][mq * 16 + g + 8] + redS[1][mq * 16 + g + 8]) * (1.f / DD);
    float v0 = fmaxf((redQ[0][mq * 16 + g] + redQ[1][mq * 16 + g]) * (1.f / DD) - mu0 * mu0, 0.f);
    float v1 = fmaxf((redQ[0][mq * 16 + g + 8] + redQ[1][mq * 16 + g + 8]) * (1.f / DD) - mu1 * mu1, 0.f);
    float rst0 = rsqrtf(v0 + 1e-3f), rst1 = rsqrtf(v1 + 1e-3f);
    #pragma unroll
    for (int nt = 0; nt < 8; nt++) {
        int col = nh * 64 + nt * 8 + 2 * tg;
        float2 gm = *(const float2*)&g2[col];
        float2 bt = *(const float2*)&be2[col];
        float2 lo = {(acc[nt][0] - mu0) * rst0 * gm.x + bt.x,
                     (acc[nt][1] - mu0) * rst0 * gm.y + bt.y};
        float2 hi = {(acc[nt][2] - mu1) * rst1 * gm.x + bt.x,
                     (acc[nt][3] - mu1) * rst1 * gm.y + bt.y};
        *(float2*)&g_x[(size_t)r0 * DD + col] = lo;
        *(float2*)&g_x[(size_t)r1 * DD + col] = hi;
    }
}

// ---------------- masked mean-pool + MLP head + sigmoid ----------------
__global__ __launch_bounds__(256) void head_kernel(
    const int* __restrict__ length,
    const float* __restrict__ Wm1, const float* __restrict__ bm1,
    const float* __restrict__ Wm2, const float* __restrict__ bm2,
    float* __restrict__ out) {
    int b = blockIdx.x;
    int t = threadIdx.x;
    __shared__ float part[2][DD];
    __shared__ float agg[DD];
    __shared__ float hh[MLPH];
    __shared__ float red[8];
    int cnt = length[b] + 1;
    int d = t & 127, grp = t >> 7;
    float s0 = 0.f, s1 = 0.f, s2 = 0.f, s3 = 0.f;
    int ss = grp;
    for (; ss + 6 < cnt; ss += 8) {
        s0 += g_x[(b * SS + ss) * DD + d];
        s1 += g_x[(b * SS + ss + 2) * DD + d];
        s2 += g_x[(b * SS + ss + 4) * DD + d];
        s3 += g_x[(b * SS + ss + 6) * DD + d];
    }
    for (; ss < cnt; ss += 2) s0 += g_x[(b * SS + ss) * DD + d];
    part[grp][d] = s0 + s1 + s2 + s3;
    __syncthreads();
    if (t < DD) agg[t] = (part[0][t] + part[1][t]) / (float)cnt;
    __syncthreads();
    {
        float acc = bm1[t];
        #pragma unroll 8
        for (int k = 0; k < DD; k++) acc += agg[k] * Wm1[k * MLPH + t];
        hh[t] = fmaxf(acc, 0.f);
    }
    __syncthreads();
    float v = hh[t] * Wm2[t];
    #pragma unroll
    for (int o = 16; o > 0; o >>= 1) v += __shfl_xor_sync(0xffffffff, v, o);
    if ((t & 31) == 0) red[t >> 5] = v;
    __syncthreads();
    if (t == 0) {
        float s = 0.f;
        #pragma unroll
        for (int i = 0; i < 8; i++) s += red[i];
        s += bm2[0];
        out[b] = 1.f / (1.f + __expf(-s));
    }
}

// ---------------- launch ----------------
extern "C" void kernel_launch(void* const* d_in, const int* in_sizes, int n_in,
                              void* d_out, int out_size) {
    (void)in_sizes; (void)n_in; (void)out_size;
    const float* demo       = (const float*)d_in[0];
    const float* times      = (const float*)d_in[1];
    const float* values     = (const float*)d_in[2];
    const int*   length     = (const int*)d_in[3];
    const float* timescales = (const float*)d_in[4];
    const float* W_demo = (const float*)d_in[5];
    const float* b_demo = (const float*)d_in[6];
    const float* W_val  = (const float*)d_in[7];
    const float* b_val  = (const float*)d_in[8];
    const float* Wq = (const float*)d_in[9];
    const float* bq = (const float*)d_in[10];
    const float* Wk = (const float*)d_in[11];
    const float* bk = (const float*)d_in[12];
    const float* Wv = (const float*)d_in[13];
    const float* bv = (const float*)d_in[14];
    const float* Wo = (const float*)d_in[15];
    const float* bo = (const float*)d_in[16];
    const float* ln1g = (const float*)d_in[17];
    const float* ln1b = (const float*)d_in[18];
    const float* W1 = (const float*)d_in[19];
    const float* b1 = (const float*)d_in[20];
    const float* W2 = (const float*)d_in[21];
    const float* b2 = (const float*)d_in[22];
    const float* ln2g = (const float*)d_in[23];
    const float* ln2b = (const float*)d_in[24];
    const float* Wm1 = (const float*)d_in[25];
    const float* bm1 = (const float*)d_in[26];
    const float* Wm2 = (const float*)d_in[27];
    const float* bm2 = (const float*)d_in[28];
    float* out = (float*)d_out;

    cudaFuncSetAttribute(qkv_mma_kernel, cudaFuncAttributeMaxDynamicSharedMemorySize, GEMM_SMEM_BYTES);
    cudaFuncSetAttribute(oproj_ln_mma_kernel, cudaFuncAttributeMaxDynamicSharedMemorySize, GEMM_SMEM_BYTES);
    cudaFuncSetAttribute(ffn1_mma_kernel, cudaFuncAttributeMaxDynamicSharedMemorySize, GEMM_SMEM_BYTES);
    cudaFuncSetAttribute(ffn2_ln_mma_kernel, cudaFuncAttributeMaxDynamicSharedMemorySize, GEMM_SMEM_BYTES);

    embed_kernel<<<(BB * SS * DD + 255) / 256, 256>>>(
        demo, times, values, timescales, W_demo, b_demo, W_val, b_val, length);

    int ntiles = BB * SS / 64;
    for (int l = 0; l < NLAY; l++) {
        dim3 gq(ntiles, 3);
        qkv_mma_kernel<<<gq, 256, GEMM_SMEM_BYTES>>>(length,
            Wq + l * DD * DD, bq + l * DD,
            Wk + l * DD * DD, bk + l * DD,
            Wv + l * DD * DD, bv + l * DD);
        dim3 ag(SS / 64, HH, BB);
        attn_mma_kernel<<<ag, 128>>>(length);
        oproj_ln_mma_kernel<<<ntiles, 256, GEMM_SMEM_BYTES>>>(length,
            Wo + l * DD * DD, bo + l * DD, ln1g + l * DD, ln1b + l * DD);
        dim3 gf(ntiles, 4);
        ffn1_mma_kernel<<<gf, 256, GEMM_SMEM_BYTES>>>(length, W1 + l * DD * DFF, b1 + l * DFF);
        ffn2_ln_mma_kernel<<<ntiles, 256, GEMM_SMEM_BYTES>>>(length,
            W2 + l * DFF * DD, b2 + l * DD, ln2g + l * DD, ln2b + l * DD);
    }

    head_kernel<<<BB, 256>>>(length, Wm1, bm1, Wm2, bm2, out);
}